// round 14
// baseline (speedup 1.0000x reference)
#include <cuda_runtime.h>
#include <cuda_fp16.h>
#include <mma.h>
#include <cstdint>

using namespace nvcuda;

#define NN 100000
#define FF 128
#define EE 1600000
#define CNT_OFF (NN + 4)

// Scratch (static device arrays — no allocation APIs allowed)
__device__ __half g_hs[(size_t)NN * FF];    // fp16 dinv*(x@W0+b0)
__device__ __half g_aggh[(size_t)NN * FF];  // fp16 relu(layer-0 aggregation)
__device__ __half g_hs2[(size_t)NN * FF];   // fp16 dinv*(aggh@W1+b1)
__device__ __half g_w0h[FF * FF];
__device__ __half g_w1h[FF * FF];
__device__ float  g_dinv[NN];
__device__ int    g_cnts[2 * (NN + 4)];     // [0,NN+4): rowcnt, [NN+4,..): colcnt
__device__ int    g_rowstart[NN + 1];
__device__ int    g_cursor[NN];
__device__ int    g_colidx[EE];
__device__ int    g_bsums[128];

// ---------------------------------------------------------------------------
// Init: zero the count arrays AND convert both weight matrices to fp16.
// ---------------------------------------------------------------------------
__global__ void k_init(const float* __restrict__ W0, const float* __restrict__ W1) {
    int i = blockIdx.x * blockDim.x + threadIdx.x;  // 0..8191
    {
        const float* W = (i < 4096) ? W0 : W1;
        __half* Wh = (i < 4096) ? g_w0h : g_w1h;
        int k = i & 4095;
        float4 v = ((const float4*)W)[k];
        __half2 h0 = __floats2half2_rn(v.x, v.y);
        __half2 h1 = __floats2half2_rn(v.z, v.w);
        uint2 p; p.x = *(uint32_t*)&h0; p.y = *(uint32_t*)&h1;
        ((uint2*)Wh)[k] = p;
    }
    int4* cz = (int4*)g_cnts;
    const int total = (2 * (NN + 4)) / 4;
    for (int k = i; k < total; k += 8192)
        cz[k] = make_int4(0, 0, 0, 0);
}

// ---------------------------------------------------------------------------
// CSR build + degrees
// ---------------------------------------------------------------------------
__global__ void k_hist(const int* __restrict__ row, const int* __restrict__ col, int e) {
    int i = blockIdx.x * blockDim.x + threadIdx.x;
    int base = i * 4;
    if (base + 3 < e) {
        int4 r = *(const int4*)&row[base];
        int4 c = *(const int4*)&col[base];
        atomicAdd(&g_cnts[r.x], 1); atomicAdd(&g_cnts[r.y], 1);
        atomicAdd(&g_cnts[r.z], 1); atomicAdd(&g_cnts[r.w], 1);
        atomicAdd(&g_cnts[CNT_OFF + c.x], 1); atomicAdd(&g_cnts[CNT_OFF + c.y], 1);
        atomicAdd(&g_cnts[CNT_OFF + c.z], 1); atomicAdd(&g_cnts[CNT_OFF + c.w], 1);
    } else {
        for (int k = base; k < e; k++) {
            atomicAdd(&g_cnts[row[k]], 1);
            atomicAdd(&g_cnts[CNT_OFF + col[k]], 1);
        }
    }
}

// dinv only needs colcnt -> runs right after hist, unblocking GEMM-0 early.
__global__ void k_dinv(int n) {
    int i = blockIdx.x * blockDim.x + threadIdx.x;
    if (i < n) g_dinv[i] = rsqrtf((float)g_cnts[CNT_OFF + i] + 1.0f);
}

__global__ void k_scan_partial(int n) {
    __shared__ int ts[256];
    const int t = threadIdx.x;
    const int base = blockIdx.x * 1024 + t * 4;

    int4 v = make_int4(0, 0, 0, 0);
    if (base < n) v = *(const int4*)&g_cnts[base];

    int s = v.x + v.y + v.z + v.w;
    ts[t] = s;
    __syncthreads();
#pragma unroll
    for (int off = 1; off < 256; off <<= 1) {
        int u = (t >= off) ? ts[t - off] : 0;
        __syncthreads();
        ts[t] += u;
        __syncthreads();
    }
    int ex = ts[t] - s;

    if (base     < n) g_rowstart[base]     = ex;
    if (base + 1 < n) g_rowstart[base + 1] = ex + v.x;
    if (base + 2 < n) g_rowstart[base + 2] = ex + v.x + v.y;
    if (base + 3 < n) g_rowstart[base + 3] = ex + v.x + v.y + v.z;
    if (t == 255) g_bsums[blockIdx.x] = ts[255];
}

__global__ void k_scan_add(int n, int nb) {
    __shared__ int bs[128];
    const int t = threadIdx.x;

    if (t < 128) {
        int s = (t < nb) ? g_bsums[t] : 0;
        bs[t] = s;
        __syncthreads();
#pragma unroll
        for (int off = 1; off < 128; off <<= 1) {
            int u = (t >= off) ? bs[t - off] : 0;
            __syncthreads();
            bs[t] += u;
            __syncthreads();
        }
        bs[t] -= s;
    } else {
        __syncthreads();
#pragma unroll
        for (int off = 1; off < 128; off <<= 1) {
            __syncthreads();
            __syncthreads();
        }
    }
    __syncthreads();

    int i = blockIdx.x * blockDim.x + t;
    if (i < n) {
        int v = g_rowstart[i] + bs[i >> 10];
        g_rowstart[i] = v;
        g_cursor[i] = v;
        if (i == n - 1) g_rowstart[n] = v + g_cnts[i];
    }
}

__global__ void k_fill(const int* __restrict__ row, const int* __restrict__ col, int e) {
    int i = blockIdx.x * blockDim.x + threadIdx.x;
    int base = i * 4;
    if (base + 3 < e) {
        int4 r = *(const int4*)&row[base];
        int4 c = *(const int4*)&col[base];
        g_colidx[atomicAdd(&g_cursor[r.x], 1)] = c.x;
        g_colidx[atomicAdd(&g_cursor[r.y], 1)] = c.y;
        g_colidx[atomicAdd(&g_cursor[r.z], 1)] = c.z;
        g_colidx[atomicAdd(&g_cursor[r.w], 1)] = c.w;
    } else {
        for (int k = base; k < e; k++)
            g_colidx[atomicAdd(&g_cursor[row[k]], 1)] = col[k];
    }
}

// ---------------------------------------------------------------------------
// Persistent W-resident tensor-core GEMM:
//   HSout[n,128] (fp16) = dinv * (A[n,128] @ W + b)
// ---------------------------------------------------------------------------
#define AS_STRIDE 136   // halves
#define CS_STRIDE 132   // floats
#define W_BYTES   (128 * AS_STRIDE * 2)
#define AC_BYTES  (64 * CS_STRIDE * 4)
#define GEMM_SMEM (W_BYTES + AC_BYTES)

template <bool A_FP32>
__launch_bounds__(256)
__global__ void k_gemm(const void* __restrict__ Ain,
                       const __half* __restrict__ Wh,
                       const float* __restrict__ b,
                       __half* __restrict__ HSout,
                       int n, int ntiles) {
    extern __shared__ __align__(256) char smem[];
    __half* Ws = (__half*)smem;
    __half* As = (__half*)(smem + W_BYTES);
    float*  Cs = (float*)(smem + W_BYTES);

    const int t = threadIdx.x;
    const int w = t >> 5;
    const int wr = w >> 1;
    const int wc = w & 1;

    {
        const uint4* Wv = (const uint4*)Wh;
#pragma unroll
        for (int j = 0; j < 8; j++) {
            int idx = t + j * 256;
            int r = idx >> 4;
            int c = idx & 15;
            *(uint4*)&Ws[r * AS_STRIDE + c * 8] = Wv[r * 16 + c];
        }
    }
    __syncthreads();

    for (int tile = blockIdx.x; tile < ntiles; tile += gridDim.x) {
        const int row0 = tile * 64;

        if (A_FP32) {
            const float4* Av = (const float4*)Ain;
#pragma unroll
            for (int j = 0; j < 8; j++) {
                int idx = t + j * 256;
                int r = idx >> 5;
                int cc = idx & 31;
                int grow = row0 + r;
                float4 v = make_float4(0.f, 0.f, 0.f, 0.f);
                if (grow < n) v = Av[(size_t)grow * 32 + cc];
                __half2 h0 = __floats2half2_rn(v.x, v.y);
                __half2 h1 = __floats2half2_rn(v.z, v.w);
                uint2 p; p.x = *(uint32_t*)&h0; p.y = *(uint32_t*)&h1;
                *(uint2*)&As[r * AS_STRIDE + cc * 4] = p;
            }
        } else {
            const uint4* Av = (const uint4*)Ain;
#pragma unroll
            for (int j = 0; j < 4; j++) {
                int idx = t + j * 256;
                int r = idx >> 4;
                int cc = idx & 15;
                int grow = row0 + r;
                uint4 v = make_uint4(0u, 0u, 0u, 0u);
                if (grow < n) v = Av[(size_t)grow * 16 + cc];
                *(uint4*)&As[r * AS_STRIDE + cc * 8] = v;
            }
        }
        __syncthreads();

        wmma::fragment<wmma::accumulator, 16, 16, 16, float> acc[4];
#pragma unroll
        for (int j = 0; j < 4; j++) wmma::fill_fragment(acc[j], 0.0f);

#pragma unroll
        for (int k = 0; k < 8; k++) {
            wmma::fragment<wmma::matrix_a, 16, 16, 16, __half, wmma::row_major> af;
            wmma::load_matrix_sync(af, As + (wr * 16) * AS_STRIDE + k * 16, AS_STRIDE);
#pragma unroll
            for (int j = 0; j < 4; j++) {
                wmma::fragment<wmma::matrix_b, 16, 16, 16, __half, wmma::row_major> bf;
                wmma::load_matrix_sync(bf, Ws + (k * 16) * AS_STRIDE + wc * 64 + j * 16, AS_STRIDE);
                wmma::mma_sync(acc[j], af, bf, acc[j]);
            }
        }
        __syncthreads();

#pragma unroll
        for (int j = 0; j < 4; j++)
            wmma::store_matrix_sync(Cs + (wr * 16) * CS_STRIDE + wc * 64 + j * 16,
                                    acc[j], CS_STRIDE, wmma::mem_row_major);
        __syncthreads();

#pragma unroll
        for (int j = 0; j < 4; j++) {
            int idx = t + j * 256;
            int r = idx >> 4;
            int c = idx & 15;
            int grow = row0 + r;
            if (grow < n) {
                float4 f0 = *(float4*)&Cs[r * CS_STRIDE + c * 8];
                float4 f1 = *(float4*)&Cs[r * CS_STRIDE + c * 8 + 4];
                float4 b0 = ((const float4*)b)[c * 2];
                float4 b1 = ((const float4*)b)[c * 2 + 1];
                float d = g_dinv[grow];
                __half2 h0 = __floats2half2_rn((f0.x + b0.x) * d, (f0.y + b0.y) * d);
                __half2 h1 = __floats2half2_rn((f0.z + b0.z) * d, (f0.w + b0.w) * d);
                __half2 h2 = __floats2half2_rn((f1.x + b1.x) * d, (f1.y + b1.y) * d);
                __half2 h3 = __floats2half2_rn((f1.z + b1.z) * d, (f1.w + b1.w) * d);
                uint4 p;
                p.x = *(uint32_t*)&h0; p.y = *(uint32_t*)&h1;
                p.z = *(uint32_t*)&h2; p.w = *(uint32_t*)&h3;
                ((uint4*)HSout)[(size_t)grow * 16 + c] = p;
            }
        }
        __syncthreads();
    }
}

// ---------------------------------------------------------------------------
// Gather (plain sum — hs has dinv folded):
//   res[i] = dinv[i] * (hs[i] + sum_{j in N(i)} hs[j])
// MODE 0: relu, fp16 out.  MODE 1: log_softmax, fp32 out.
// ---------------------------------------------------------------------------
template <int MODE>
__global__ void k_gather(const __half* __restrict__ hs,
                         void* __restrict__ out,
                         int n) {
    int warp = (blockIdx.x * blockDim.x + threadIdx.x) >> 5;
    int lane = threadIdx.x & 31;
    if (warp >= n) return;

    int s = g_rowstart[warp];
    int t_ = g_rowstart[warp + 1];
    float di = g_dinv[warp];

    const uint2* hsv = (const uint2*)hs;

    float4 acc;
    {
        uint2 raw = hsv[(size_t)warp * 32 + lane];
        float2 f0 = __half22float2(*(__half2*)&raw.x);
        float2 f1 = __half22float2(*(__half2*)&raw.y);
        acc.x = f0.x; acc.y = f0.y; acc.z = f1.x; acc.w = f1.y;
    }

#define ACC_ADD(raw) { \
    float2 a0 = __half22float2(*(__half2*)&(raw).x); \
    float2 a1 = __half22float2(*(__half2*)&(raw).y); \
    acc.x += a0.x; acc.y += a0.y; acc.z += a1.x; acc.w += a1.y; }

    for (int e0 = s; e0 < t_; e0 += 32) {
        int idx = e0 + lane;
        int j = 0;
        if (idx < t_) j = g_colidx[idx];
        int cnt = min(32, t_ - e0);
        int k = 0;
        for (; k + 4 <= cnt; k += 4) {
            int j0 = __shfl_sync(0xffffffffu, j, k);
            int j1 = __shfl_sync(0xffffffffu, j, k + 1);
            int j2 = __shfl_sync(0xffffffffu, j, k + 2);
            int j3 = __shfl_sync(0xffffffffu, j, k + 3);
            uint2 r0 = hsv[(size_t)j0 * 32 + lane];
            uint2 r1 = hsv[(size_t)j1 * 32 + lane];
            uint2 r2 = hsv[(size_t)j2 * 32 + lane];
            uint2 r3 = hsv[(size_t)j3 * 32 + lane];
            ACC_ADD(r0) ACC_ADD(r1) ACC_ADD(r2) ACC_ADD(r3)
        }
        for (; k < cnt; k++) {
            int jj = __shfl_sync(0xffffffffu, j, k);
            uint2 raw = hsv[(size_t)jj * 32 + lane];
            ACC_ADD(raw)
        }
    }
#undef ACC_ADD

    acc.x *= di; acc.y *= di; acc.z *= di; acc.w *= di;

    if (MODE == 0) {
        acc.x = fmaxf(acc.x, 0.f); acc.y = fmaxf(acc.y, 0.f);
        acc.z = fmaxf(acc.z, 0.f); acc.w = fmaxf(acc.w, 0.f);
        __half2 h0 = __floats2half2_rn(acc.x, acc.y);
        __half2 h1 = __floats2half2_rn(acc.z, acc.w);
        uint2 p; p.x = *(uint32_t*)&h0; p.y = *(uint32_t*)&h1;
        ((uint2*)out)[(size_t)warp * 32 + lane] = p;
    } else {
        float mx = fmaxf(fmaxf(acc.x, acc.y), fmaxf(acc.z, acc.w));
#pragma unroll
        for (int o = 16; o; o >>= 1) mx = fmaxf(mx, __shfl_xor_sync(0xffffffffu, mx, o));
        float sum = expf(acc.x - mx) + expf(acc.y - mx) + expf(acc.z - mx) + expf(acc.w - mx);
#pragma unroll
        for (int o = 16; o; o >>= 1) sum += __shfl_xor_sync(0xffffffffu, sum, o);
        float lse = mx + logf(sum);
        acc.x -= lse; acc.y -= lse; acc.z -= lse; acc.w -= lse;
        ((float4*)out)[(size_t)warp * 32 + lane] = acc;
    }
}

// ---------------------------------------------------------------------------
// Launch — dinv computed right after hist so GEMM-0 forks before the scan,
// overlapping the entire scan+fill chain.
// ---------------------------------------------------------------------------
extern "C" void kernel_launch(void* const* d_in, const int* in_sizes, int n_in,
                              void* d_out, int out_size) {
    const float* x  = (const float*)d_in[0];
    const float* W0 = (const float*)d_in[1];
    const float* b0 = (const float*)d_in[2];
    const float* W1 = (const float*)d_in[3];
    const float* b1 = (const float*)d_in[4];
    const int* row  = (const int*)d_in[5];
    const int* col  = (const int*)d_in[6];
    float* out = (float*)d_out;

    const int n = in_sizes[0] / FF;   // 100000
    const int e = in_sizes[5];        // 1600000

    __half* hs;   cudaGetSymbolAddress((void**)&hs,   g_hs);
    __half* aggh; cudaGetSymbolAddress((void**)&aggh, g_aggh);
    __half* hs2;  cudaGetSymbolAddress((void**)&hs2,  g_hs2);
    __half* w0h;  cudaGetSymbolAddress((void**)&w0h,  g_w0h);
    __half* w1h;  cudaGetSymbolAddress((void**)&w1h,  g_w1h);

    cudaFuncSetAttribute(k_gemm<true>,  cudaFuncAttributeMaxDynamicSharedMemorySize, GEMM_SMEM);
    cudaFuncSetAttribute(k_gemm<false>, cudaFuncAttributeMaxDynamicSharedMemorySize, GEMM_SMEM);

    const int nb = (n + 1023) / 1024;
    const int ntiles = (n + 63) / 64;
    const int gemm_grid = ntiles < 444 ? ntiles : 444;
    const int gath_blocks = (n * 32 + 255) / 256;

    // Single side stream + events (created per call, intentionally not
    // destroyed — the pattern that passes the teardown memory check).
    cudaStream_t sA;
    cudaStreamCreate(&sA);
    cudaEvent_t evDinv, evJoin;
    cudaEventCreateWithFlags(&evDinv, cudaEventDisableTiming);
    cudaEventCreateWithFlags(&evJoin, cudaEventDisableTiming);

    // Main stream: init -> hist -> dinv (dinv only needs colcnt!)
    k_init<<<32, 256>>>(W0, W1);
    k_hist<<<(e / 4 + 255) / 256, 256>>>(row, col, e);
    k_dinv<<<(n + 255) / 256, 256>>>(n);
    cudaEventRecord(evDinv, 0);

    // Side stream: GEMM0 forks here, overlapping scan_partial+scan_add+fill
    cudaStreamWaitEvent(sA, evDinv, 0);
    k_gemm<true><<<gemm_grid, 256, GEMM_SMEM, sA>>>(x, w0h, b0, hs, n, ntiles);
    cudaEventRecord(evJoin, sA);

    // Main stream: scan + CSR fill
    k_scan_partial<<<nb, 256>>>(n);
    k_scan_add<<<(n + 255) / 256, 256>>>(n, nb);
    k_fill<<<(e / 4 + 255) / 256, 256>>>(row, col, e);

    // Join
    cudaStreamWaitEvent(0, evJoin, 0);

    // Layer 0 aggregation (plain sum; relu; fp16)
    k_gather<0><<<gath_blocks, 256>>>(hs, aggh, n);

    // Layer 1
    k_gemm<false><<<gemm_grid, 256, GEMM_SMEM>>>(aggh, w1h, b1, hs2, n, ntiles);
    k_gather<1><<<gath_blocks, 256>>>(hs2, out, n);
}

// round 15
// speedup vs baseline: 1.0322x; 1.0322x over previous
#include <cuda_runtime.h>
#include <cuda_fp16.h>
#include <mma.h>
#include <cstdint>

using namespace nvcuda;

#define NN 100000
#define FF 128
#define EE 1600000
#define CNT_OFF (NN + 4)

// Scratch (static device arrays — no allocation APIs allowed)
__device__ __half g_hs[(size_t)NN * FF];    // fp16 dinv*(x@W0+b0)
__device__ __half g_aggh[(size_t)NN * FF];  // fp16 relu(layer-0 aggregation)
__device__ __half g_hs2[(size_t)NN * FF];   // fp16 dinv*(aggh@W1+b1)
__device__ __half g_w0h[FF * FF];
__device__ __half g_w1h[FF * FF];
__device__ float  g_dinv[NN];
__device__ int    g_cnts[2 * (NN + 4)];
__device__ int    g_rowstart[NN + 1];
__device__ int    g_cursor[NN];
__device__ int    g_colidx[EE];
__device__ int    g_bsums[128];

// ---------------------------------------------------------------------------
// Init: zero counts + convert both weights to fp16
// ---------------------------------------------------------------------------
__global__ void k_init(const float* __restrict__ W0, const float* __restrict__ W1) {
    int i = blockIdx.x * blockDim.x + threadIdx.x;  // 0..8191
    {
        const float* W = (i < 4096) ? W0 : W1;
        __half* Wh = (i < 4096) ? g_w0h : g_w1h;
        int k = i & 4095;
        float4 v = ((const float4*)W)[k];
        __half2 h0 = __floats2half2_rn(v.x, v.y);
        __half2 h1 = __floats2half2_rn(v.z, v.w);
        uint2 p; p.x = *(uint32_t*)&h0; p.y = *(uint32_t*)&h1;
        ((uint2*)Wh)[k] = p;
    }
    int4* cz = (int4*)g_cnts;
    const int total = (2 * (NN + 4)) / 4;
    for (int k = i; k < total; k += 8192)
        cz[k] = make_int4(0, 0, 0, 0);
}

// ---------------------------------------------------------------------------
// CSR build + degrees
// ---------------------------------------------------------------------------
__global__ void k_hist(const int* __restrict__ row, const int* __restrict__ col, int e) {
    int i = blockIdx.x * blockDim.x + threadIdx.x;
    int base = i * 4;
    if (base + 3 < e) {
        int4 r = *(const int4*)&row[base];
        int4 c = *(const int4*)&col[base];
        atomicAdd(&g_cnts[r.x], 1); atomicAdd(&g_cnts[r.y], 1);
        atomicAdd(&g_cnts[r.z], 1); atomicAdd(&g_cnts[r.w], 1);
        atomicAdd(&g_cnts[CNT_OFF + c.x], 1); atomicAdd(&g_cnts[CNT_OFF + c.y], 1);
        atomicAdd(&g_cnts[CNT_OFF + c.z], 1); atomicAdd(&g_cnts[CNT_OFF + c.w], 1);
    } else {
        for (int k = base; k < e; k++) {
            atomicAdd(&g_cnts[row[k]], 1);
            atomicAdd(&g_cnts[CNT_OFF + col[k]], 1);
        }
    }
}

__global__ void k_scan_partial(int n) {
    __shared__ int ts[256];
    const int t = threadIdx.x;
    const int base = blockIdx.x * 1024 + t * 4;

    int4 v = make_int4(0, 0, 0, 0);
    if (base < n) v = *(const int4*)&g_cnts[base];

    int s = v.x + v.y + v.z + v.w;
    ts[t] = s;
    __syncthreads();
#pragma unroll
    for (int off = 1; off < 256; off <<= 1) {
        int u = (t >= off) ? ts[t - off] : 0;
        __syncthreads();
        ts[t] += u;
        __syncthreads();
    }
    int ex = ts[t] - s;

    if (base     < n) g_rowstart[base]     = ex;
    if (base + 1 < n) g_rowstart[base + 1] = ex + v.x;
    if (base + 2 < n) g_rowstart[base + 2] = ex + v.x + v.y;
    if (base + 3 < n) g_rowstart[base + 3] = ex + v.x + v.y + v.z;
    if (t == 255) g_bsums[blockIdx.x] = ts[255];
}

__global__ void k_scan_add_dinv(int n, int nb) {
    __shared__ int bs[128];
    const int t = threadIdx.x;

    if (t < 128) {
        int s = (t < nb) ? g_bsums[t] : 0;
        bs[t] = s;
        __syncthreads();
#pragma unroll
        for (int off = 1; off < 128; off <<= 1) {
            int u = (t >= off) ? bs[t - off] : 0;
            __syncthreads();
            bs[t] += u;
            __syncthreads();
        }
        bs[t] -= s;
    } else {
        __syncthreads();
#pragma unroll
        for (int off = 1; off < 128; off <<= 1) {
            __syncthreads();
            __syncthreads();
        }
    }
    __syncthreads();

    int i = blockIdx.x * blockDim.x + t;
    if (i < n) {
        int v = g_rowstart[i] + bs[i >> 10];
        g_rowstart[i] = v;
        g_cursor[i] = v;
        g_dinv[i] = rsqrtf((float)g_cnts[CNT_OFF + i] + 1.0f);
        if (i == n - 1) g_rowstart[n] = v + g_cnts[i];
    }
}

__global__ void k_fill(const int* __restrict__ row, const int* __restrict__ col, int e) {
    int i = blockIdx.x * blockDim.x + threadIdx.x;
    int base = i * 4;
    if (base + 3 < e) {
        int4 r = *(const int4*)&row[base];
        int4 c = *(const int4*)&col[base];
        g_colidx[atomicAdd(&g_cursor[r.x], 1)] = c.x;
        g_colidx[atomicAdd(&g_cursor[r.y], 1)] = c.y;
        g_colidx[atomicAdd(&g_cursor[r.z], 1)] = c.z;
        g_colidx[atomicAdd(&g_cursor[r.w], 1)] = c.w;
    } else {
        for (int k = base; k < e; k++)
            g_colidx[atomicAdd(&g_cursor[row[k]], 1)] = col[k];
    }
}

// ---------------------------------------------------------------------------
// W-in-register tensor-core GEMM: HSout = dinv * (A @ W + b), fp16 out.
// Each warp owns 16 output cols; its 8 matrix_b fragments live in registers
// (loaded once from global). A tile staged in smem; next tile's global loads
// prefetched into registers during MMA. Epilogue via per-warp smem scratch.
// ---------------------------------------------------------------------------
#define ASTRIDE 136                      // halves
#define SCR_STRIDE 24                    // floats (96B rows, 16B-aligned)
#define A_BYTES (64 * ASTRIDE * 2)       // 17408
#define SCR_BYTES (8 * 16 * SCR_STRIDE * 4)  // 12288
#define GEMM_SMEM (A_BYTES + SCR_BYTES)  // 29696

template <bool A_FP32>
__launch_bounds__(256)
__global__ void k_gemm(const void* __restrict__ Ain,
                       const __half* __restrict__ Wh,
                       const float* __restrict__ b,
                       __half* __restrict__ HSout,
                       int n, int ntiles) {
    extern __shared__ __align__(256) char smem[];
    __half* As = (__half*)smem;
    float* scr = (float*)(smem + A_BYTES) + (threadIdx.x >> 5) * 16 * SCR_STRIDE;

    const int t = threadIdx.x;
    const int w = t >> 5;
    const int lane = t & 31;
    const int r2 = lane >> 1;   // row within 16-row group handled in epilogue
    const int h8 = lane & 1;    // which 8-col half of the warp's 16-col strip

    // B fragments resident in registers (W never re-read after this)
    wmma::fragment<wmma::matrix_b, 16, 16, 16, __half, wmma::row_major> bw[8];
#pragma unroll
    for (int k = 0; k < 8; k++)
        wmma::load_matrix_sync(bw[k], Wh + k * 16 * 128 + w * 16, 128);

    // bias for this warp-half's 8 columns
    float4 bias0 = ((const float4*)b)[w * 4 + h8 * 2];
    float4 bias1 = ((const float4*)b)[w * 4 + h8 * 2 + 1];

    // register prefetch buffers
    float4 pf32[8];
    uint4  pf16[4];

    int tile = blockIdx.x;
    // prefetch first tile
    if (tile < ntiles) {
        int row0 = tile * 64;
        if (A_FP32) {
            const float4* Av = (const float4*)Ain;
#pragma unroll
            for (int j = 0; j < 8; j++) {
                int idx = t + j * 256;
                int grow = row0 + (idx >> 5);
                pf32[j] = (grow < n) ? Av[(size_t)grow * 32 + (idx & 31)]
                                     : make_float4(0.f, 0.f, 0.f, 0.f);
            }
        } else {
            const uint4* Av = (const uint4*)Ain;
#pragma unroll
            for (int j = 0; j < 4; j++) {
                int idx = t + j * 256;
                int grow = row0 + (idx >> 4);
                pf16[j] = (grow < n) ? Av[(size_t)grow * 16 + (idx & 15)]
                                     : make_uint4(0u, 0u, 0u, 0u);
            }
        }
    }

    for (; tile < ntiles; tile += gridDim.x) {
        const int row0 = tile * 64;

        // commit prefetched regs to smem
        if (A_FP32) {
#pragma unroll
            for (int j = 0; j < 8; j++) {
                int idx = t + j * 256;
                int r = idx >> 5, cc = idx & 31;
                __half2 h0 = __floats2half2_rn(pf32[j].x, pf32[j].y);
                __half2 h1 = __floats2half2_rn(pf32[j].z, pf32[j].w);
                uint2 p; p.x = *(uint32_t*)&h0; p.y = *(uint32_t*)&h1;
                *(uint2*)&As[r * ASTRIDE + cc * 4] = p;
            }
        } else {
#pragma unroll
            for (int j = 0; j < 4; j++) {
                int idx = t + j * 256;
                int r = idx >> 4, cc = idx & 15;
                *(uint4*)&As[r * ASTRIDE + cc * 8] = pf16[j];
            }
        }
        __syncthreads();

        // issue next tile's global loads (latency hidden by MMA below)
        int next = tile + gridDim.x;
        if (next < ntiles) {
            int nrow0 = next * 64;
            if (A_FP32) {
                const float4* Av = (const float4*)Ain;
#pragma unroll
                for (int j = 0; j < 8; j++) {
                    int idx = t + j * 256;
                    int grow = nrow0 + (idx >> 5);
                    pf32[j] = (grow < n) ? Av[(size_t)grow * 32 + (idx & 31)]
                                         : make_float4(0.f, 0.f, 0.f, 0.f);
                }
            } else {
                const uint4* Av = (const uint4*)Ain;
#pragma unroll
                for (int j = 0; j < 4; j++) {
                    int idx = t + j * 256;
                    int grow = nrow0 + (idx >> 4);
                    pf16[j] = (grow < n) ? Av[(size_t)grow * 16 + (idx & 15)]
                                         : make_uint4(0u, 0u, 0u, 0u);
                }
            }
        }

        // MMA + per-warp epilogue, one 16-row group at a time
#pragma unroll
        for (int r = 0; r < 4; r++) {
            wmma::fragment<wmma::accumulator, 16, 16, 16, float> acc;
            wmma::fill_fragment(acc, 0.0f);
#pragma unroll
            for (int k = 0; k < 8; k++) {
                wmma::fragment<wmma::matrix_a, 16, 16, 16, __half, wmma::row_major> af;
                wmma::load_matrix_sync(af, As + (r * 16) * ASTRIDE + k * 16, ASTRIDE);
                wmma::mma_sync(acc, af, bw[k], acc);
            }
            wmma::store_matrix_sync(scr, acc, SCR_STRIDE, wmma::mem_row_major);
            __syncwarp();

            int grow = row0 + r * 16 + r2;
            if (grow < n) {
                float4 f0 = *(float4*)&scr[r2 * SCR_STRIDE + h8 * 8];
                float4 f1 = *(float4*)&scr[r2 * SCR_STRIDE + h8 * 8 + 4];
                float d = g_dinv[grow];
                __half2 h0 = __floats2half2_rn((f0.x + bias0.x) * d, (f0.y + bias0.y) * d);
                __half2 h1 = __floats2half2_rn((f0.z + bias0.z) * d, (f0.w + bias0.w) * d);
                __half2 h2 = __floats2half2_rn((f1.x + bias1.x) * d, (f1.y + bias1.y) * d);
                __half2 h3 = __floats2half2_rn((f1.z + bias1.z) * d, (f1.w + bias1.w) * d);
                uint4 p;
                p.x = *(uint32_t*)&h0; p.y = *(uint32_t*)&h1;
                p.z = *(uint32_t*)&h2; p.w = *(uint32_t*)&h3;
                ((uint4*)HSout)[(size_t)grow * 16 + w * 2 + h8] = p;
            }
            __syncwarp();   // scratch reads done before next rgroup's store
        }
        __syncthreads();    // As reads done before next tile's sts
    }
}

// ---------------------------------------------------------------------------
// Gather (plain sum — hs has dinv folded):
//   res[i] = dinv[i] * (hs[i] + sum_{j in N(i)} hs[j])
// MODE 0: relu, fp16 out.  MODE 1: log_softmax, fp32 out.
// ---------------------------------------------------------------------------
template <int MODE>
__global__ void k_gather(const __half* __restrict__ hs,
                         void* __restrict__ out,
                         int n) {
    int warp = (blockIdx.x * blockDim.x + threadIdx.x) >> 5;
    int lane = threadIdx.x & 31;
    if (warp >= n) return;

    int s = g_rowstart[warp];
    int t_ = g_rowstart[warp + 1];
    float di = g_dinv[warp];

    const uint2* hsv = (const uint2*)hs;

    float4 acc;
    {
        uint2 raw = hsv[(size_t)warp * 32 + lane];
        float2 f0 = __half22float2(*(__half2*)&raw.x);
        float2 f1 = __half22float2(*(__half2*)&raw.y);
        acc.x = f0.x; acc.y = f0.y; acc.z = f1.x; acc.w = f1.y;
    }

#define ACC_ADD(raw) { \
    float2 a0 = __half22float2(*(__half2*)&(raw).x); \
    float2 a1 = __half22float2(*(__half2*)&(raw).y); \
    acc.x += a0.x; acc.y += a0.y; acc.z += a1.x; acc.w += a1.y; }

    for (int e0 = s; e0 < t_; e0 += 32) {
        int idx = e0 + lane;
        int j = 0;
        if (idx < t_) j = g_colidx[idx];
        int cnt = min(32, t_ - e0);
        int k = 0;
        for (; k + 4 <= cnt; k += 4) {
            int j0 = __shfl_sync(0xffffffffu, j, k);
            int j1 = __shfl_sync(0xffffffffu, j, k + 1);
            int j2 = __shfl_sync(0xffffffffu, j, k + 2);
            int j3 = __shfl_sync(0xffffffffu, j, k + 3);
            uint2 r0 = hsv[(size_t)j0 * 32 + lane];
            uint2 r1 = hsv[(size_t)j1 * 32 + lane];
            uint2 r2 = hsv[(size_t)j2 * 32 + lane];
            uint2 r3 = hsv[(size_t)j3 * 32 + lane];
            ACC_ADD(r0) ACC_ADD(r1) ACC_ADD(r2) ACC_ADD(r3)
        }
        for (; k < cnt; k++) {
            int jj = __shfl_sync(0xffffffffu, j, k);
            uint2 raw = hsv[(size_t)jj * 32 + lane];
            ACC_ADD(raw)
        }
    }
#undef ACC_ADD

    acc.x *= di; acc.y *= di; acc.z *= di; acc.w *= di;

    if (MODE == 0) {
        acc.x = fmaxf(acc.x, 0.f); acc.y = fmaxf(acc.y, 0.f);
        acc.z = fmaxf(acc.z, 0.f); acc.w = fmaxf(acc.w, 0.f);
        __half2 h0 = __floats2half2_rn(acc.x, acc.y);
        __half2 h1 = __floats2half2_rn(acc.z, acc.w);
        uint2 p; p.x = *(uint32_t*)&h0; p.y = *(uint32_t*)&h1;
        ((uint2*)out)[(size_t)warp * 32 + lane] = p;
    } else {
        float mx = fmaxf(fmaxf(acc.x, acc.y), fmaxf(acc.z, acc.w));
#pragma unroll
        for (int o = 16; o; o >>= 1) mx = fmaxf(mx, __shfl_xor_sync(0xffffffffu, mx, o));
        float sum = expf(acc.x - mx) + expf(acc.y - mx) + expf(acc.z - mx) + expf(acc.w - mx);
#pragma unroll
        for (int o = 16; o; o >>= 1) sum += __shfl_xor_sync(0xffffffffu, sum, o);
        float lse = mx + logf(sum);
        acc.x -= lse; acc.y -= lse; acc.z -= lse; acc.w -= lse;
        ((float4*)out)[(size_t)warp * 32 + lane] = acc;
    }
}

// ---------------------------------------------------------------------------
// Launch — R13 schedule (measured best) with the new GEMM
// ---------------------------------------------------------------------------
extern "C" void kernel_launch(void* const* d_in, const int* in_sizes, int n_in,
                              void* d_out, int out_size) {
    const float* x  = (const float*)d_in[0];
    const float* W0 = (const float*)d_in[1];
    const float* b0 = (const float*)d_in[2];
    const float* W1 = (const float*)d_in[3];
    const float* b1 = (const float*)d_in[4];
    const int* row  = (const int*)d_in[5];
    const int* col  = (const int*)d_in[6];
    float* out = (float*)d_out;

    const int n = in_sizes[0] / FF;   // 100000
    const int e = in_sizes[5];        // 1600000

    __half* hs;   cudaGetSymbolAddress((void**)&hs,   g_hs);
    __half* aggh; cudaGetSymbolAddress((void**)&aggh, g_aggh);
    __half* hs2;  cudaGetSymbolAddress((void**)&hs2,  g_hs2);
    __half* w0h;  cudaGetSymbolAddress((void**)&w0h,  g_w0h);
    __half* w1h;  cudaGetSymbolAddress((void**)&w1h,  g_w1h);

    cudaFuncSetAttribute(k_gemm<true>,  cudaFuncAttributeMaxDynamicSharedMemorySize, GEMM_SMEM);
    cudaFuncSetAttribute(k_gemm<false>, cudaFuncAttributeMaxDynamicSharedMemorySize, GEMM_SMEM);

    const int nb = (n + 1023) / 1024;
    const int ntiles = (n + 63) / 64;
    const int gemm_grid = ntiles < 304 ? ntiles : 304;   // 2 CTAs/SM resident
    const int gath_blocks = (n * 32 + 255) / 256;

    // Single side stream + events (created per call, intentionally not
    // destroyed — the pattern that passes the teardown memory check).
    cudaStream_t sA;
    cudaStreamCreate(&sA);
    cudaEvent_t evDinv, evJoin;
    cudaEventCreateWithFlags(&evDinv, cudaEventDisableTiming);
    cudaEventCreateWithFlags(&evJoin, cudaEventDisableTiming);

    // Main stream: init -> hist -> scan (+dinv)
    k_init<<<32, 256>>>(W0, W1);
    k_hist<<<(e / 4 + 255) / 256, 256>>>(row, col, e);
    k_scan_partial<<<nb, 256>>>(n);
    k_scan_add_dinv<<<(n + 255) / 256, 256>>>(n, nb);
    cudaEventRecord(evDinv, 0);

    // Side stream: GEMM0 (dinv folded) overlaps k_fill
    cudaStreamWaitEvent(sA, evDinv, 0);
    k_gemm<true><<<gemm_grid, 256, GEMM_SMEM, sA>>>(x, w0h, b0, hs, n, ntiles);
    cudaEventRecord(evJoin, sA);

    // Main stream: CSR fill
    k_fill<<<(e / 4 + 255) / 256, 256>>>(row, col, e);

    // Join
    cudaStreamWaitEvent(0, evJoin, 0);

    // Layer 0 aggregation (plain sum; relu; fp16)
    k_gather<0><<<gath_blocks, 256>>>(hs, aggh, n);

    // Layer 1
    k_gemm<false><<<gemm_grid, 256, GEMM_SMEM>>>(aggh, w1h, b1, hs2, n, ntiles);
    k_gather<1><<<gath_blocks, 256>>>(hs2, out, n);
}